// round 1
// baseline (speedup 1.0000x reference)
#include <cuda_runtime.h>
#include <cuda_bf16.h>
#include <cstdint>

// ---------------------------------------------------------------------------
// GIFNeuron: h = x @ W^T + b  (M=32768, N=512, K=512, fp32)
// then per-(b,h) sequential GIF-neuron scan over T=2048.
// Outputs flattened: spikes [B,T,H] | v_f [B,H] | theta_f [B,H]
// ---------------------------------------------------------------------------

#define M_DIM 32768   // B*T
#define N_DIM 512     // H
#define K_DIM 512     // IN
#define B_DIM 16
#define T_DIM 2048

// 64 MB scratch for h (static __device__ array: allocation-free)
__device__ float g_h[(size_t)M_DIM * N_DIM];

// ---------------------------------------------------------------------------
// Kernel 1: fp32 GEMM, C[m][n] = sum_k A[m][k] * B[n][k] + bias[n]
// A row-major [M,K], B row-major [N,K]  (both K-contiguous -> NT GEMM)
// BM=128, BN=128, BK=16, 256 threads, 8x8 per thread.
// ---------------------------------------------------------------------------
#define BM 128
#define BN 128
#define BK 16
#define TM 8
#define TN 8

__global__ __launch_bounds__(256, 2)
void gemm_nt_kernel(const float* __restrict__ A,
                    const float* __restrict__ B,
                    const float* __restrict__ bias,
                    float* __restrict__ C)
{
    __shared__ float As[BK][BM];
    __shared__ float Bs[BK][BN];

    const int bm  = blockIdx.y * BM;
    const int bn  = blockIdx.x * BN;
    const int tid = threadIdx.x;

    const int tr = (tid >> 4) * TM;   // 0..120, row offset in tile
    const int tc = (tid & 15) * TN;   // 0..120, col offset in tile

    float acc[TM][TN];
#pragma unroll
    for (int i = 0; i < TM; i++)
#pragma unroll
        for (int j = 0; j < TN; j++)
            acc[i][j] = 0.0f;

    const float* Ab = A + (size_t)bm * K_DIM;
    const float* Bb = B + (size_t)bn * K_DIM;

    for (int k0 = 0; k0 < K_DIM; k0 += BK) {
        // Load A tile (128x16) and B tile (128x16): 512 float4 each,
        // 256 threads -> 2 float4 per operand per thread, coalesced along K.
#pragma unroll
        for (int i = 0; i < 2; i++) {
            int idx = tid + i * 256;          // 0..511
            int row = idx >> 2;               // 0..127
            int kq  = (idx & 3) << 2;         // 0,4,8,12
            float4 av = *(const float4*)(Ab + (size_t)row * K_DIM + k0 + kq);
            As[kq + 0][row] = av.x;
            As[kq + 1][row] = av.y;
            As[kq + 2][row] = av.z;
            As[kq + 3][row] = av.w;
            float4 bv = *(const float4*)(Bb + (size_t)row * K_DIM + k0 + kq);
            Bs[kq + 0][row] = bv.x;
            Bs[kq + 1][row] = bv.y;
            Bs[kq + 2][row] = bv.z;
            Bs[kq + 3][row] = bv.w;
        }
        __syncthreads();

#pragma unroll
        for (int kk = 0; kk < BK; kk++) {
            float ar[TM], br[TN];
#pragma unroll
            for (int i = 0; i < TM; i++) ar[i] = As[kk][tr + i];
#pragma unroll
            for (int j = 0; j < TN; j++) br[j] = Bs[kk][tc + j];
#pragma unroll
            for (int i = 0; i < TM; i++)
#pragma unroll
                for (int j = 0; j < TN; j++)
                    acc[i][j] = fmaf(ar[i], br[j], acc[i][j]);
        }
        __syncthreads();
    }

    // Epilogue: add bias, store (vectorized float4, TN=8 -> 2 stores/row)
#pragma unroll
    for (int i = 0; i < TM; i++) {
        size_t crow = (size_t)(bm + tr + i) * N_DIM + bn + tc;
#pragma unroll
        for (int j = 0; j < TN; j += 4) {
            float4 o;
            o.x = acc[i][j + 0] + bias[bn + tc + j + 0];
            o.y = acc[i][j + 1] + bias[bn + tc + j + 1];
            o.z = acc[i][j + 2] + bias[bn + tc + j + 2];
            o.w = acc[i][j + 3] + bias[bn + tc + j + 3];
            *(float4*)(C + crow + j) = o;
        }
    }
}

// ---------------------------------------------------------------------------
// Kernel 2: GIF-neuron scan. One thread per (b, h) chain: 8192 threads.
// Sequential over T=2048; unroll x8 with batched loads to hide LDG latency.
// ---------------------------------------------------------------------------
__global__ __launch_bounds__(256)
void gif_scan_kernel(const float* __restrict__ h,
                     float* __restrict__ spikes,
                     float* __restrict__ v_out,
                     float* __restrict__ theta_out)
{
    const int idx = blockIdx.x * blockDim.x + threadIdx.x;
    if (idx >= B_DIM * N_DIM) return;
    const int b  = idx >> 9;        // / 512
    const int hh = idx & 511;

    const float* hp = h      + (size_t)b * T_DIM * N_DIM + hh;
    float*       sp = spikes + (size_t)b * T_DIM * N_DIM + hh;

    const float DECAY = 0.90483741803595952f;  // exp(-1/10)
    float v = 0.0f;
    float theta = 1.0f;

    for (int t0 = 0; t0 < T_DIM; t0 += 8) {
        float in[8];
#pragma unroll
        for (int u = 0; u < 8; u++)
            in[u] = hp[(size_t)(t0 + u) * N_DIM];

        float out[8];
#pragma unroll
        for (int u = 0; u < 8; u++) {
            // v = v*decay + i_t
            v = fmaf(v, DECAY, in[u]);
            // clamp to +/- 2*L*theta = 32*theta
            float cl = 32.0f * theta;
            v = fminf(fmaxf(v, -cl), cl);
            // spike = clip(floor(v / theta), 0, 16)
            float s = floorf(v / theta);
            s = fminf(fmaxf(s, 0.0f), 16.0f);
            // v -= spike * theta
            v = fmaf(-s, theta, v);
            // theta += alpha*spike - alpha*(theta - 1)
            theta = theta + 0.01f * s - 0.01f * (theta - 1.0f);
            out[u] = s;
        }

#pragma unroll
        for (int u = 0; u < 8; u++)
            sp[(size_t)(t0 + u) * N_DIM] = out[u];
    }

    v_out[idx]     = v;
    theta_out[idx] = theta;
}

// ---------------------------------------------------------------------------
// kernel_launch
// Inputs (metadata order): x [16,2048,512] f32, W [512,512] f32, b [512] f32
// Output: float32, spikes | v_f | theta_f
// ---------------------------------------------------------------------------
extern "C" void kernel_launch(void* const* d_in, const int* in_sizes, int n_in,
                              void* d_out, int out_size)
{
    const float* x = (const float*)d_in[0];
    const float* W = (const float*)d_in[1];
    const float* b = (const float*)d_in[2];

    float* out    = (float*)d_out;
    float* spikes = out;
    float* v_f    = out + (size_t)B_DIM * T_DIM * N_DIM;
    float* th_f   = v_f + (size_t)B_DIM * N_DIM;

    float* h;
    cudaGetSymbolAddress((void**)&h, g_h);

    dim3 gemm_grid(N_DIM / BN, M_DIM / BM);   // (4, 256)
    gemm_nt_kernel<<<gemm_grid, 256>>>(x, W, b, h);

    gif_scan_kernel<<<(B_DIM * N_DIM + 255) / 256, 256>>>(h, spikes, v_f, th_f);
}

// round 3
// speedup vs baseline: 1.0951x; 1.0951x over previous
#include <cuda_runtime.h>
#include <cuda_bf16.h>
#include <cstdint>

// ---------------------------------------------------------------------------
// GIFNeuron: h = x @ W^T + b  (M=32768, N=512, K=512, fp32)
// then per-(b,h) sequential GIF-neuron scan over T=2048.
// Outputs flattened: spikes [B,T,H] | v_f [B,H] | theta_f [B,H]
// ---------------------------------------------------------------------------

#define M_DIM 32768   // B*T
#define N_DIM 512     // H
#define K_DIM 512     // IN
#define B_DIM 16
#define T_DIM 2048

// 64 MB scratch for h (static __device__ array: allocation-free)
__device__ float g_h[(size_t)M_DIM * N_DIM];

// ---------------------------------------------------------------------------
// Packed fp32x2 helpers (sm_100+ FFMA2 path, PTX-only)
// ---------------------------------------------------------------------------
__device__ __forceinline__ void ffma2(unsigned long long& d,
                                      unsigned long long a,
                                      unsigned long long b)
{
    asm("fma.rn.f32x2 %0, %1, %2, %0;" : "+l"(d) : "l"(a), "l"(b));
}

__device__ __forceinline__ unsigned long long dup2(float x)
{
    unsigned long long r;
    asm("mov.b64 %0, {%1, %1};" : "=l"(r) : "f"(x));
    return r;
}

__device__ __forceinline__ void unpack2(unsigned long long p, float& lo, float& hi)
{
    asm("mov.b64 {%0, %1}, %2;" : "=f"(lo), "=f"(hi) : "l"(p));
}

// ---------------------------------------------------------------------------
// Kernel 1: fp32 GEMM via packed FFMA2.
// C[m][n] = sum_k A[m][k]*B[n][k] + bias[n]
// BM=128, BN=128, BK=16, 256 threads, 8x8 per thread (N packed in pairs).
// Bit-identical arithmetic to the scalar version (same fma, same k-order).
// ---------------------------------------------------------------------------
#define BM 128
#define BN 128
#define BK 16

__global__ __launch_bounds__(256, 2)
void gemm_nt_f32x2_kernel(const float* __restrict__ A,
                          const float* __restrict__ B,
                          const float* __restrict__ bias,
                          float* __restrict__ C)
{
    __shared__ unsigned long long As2[BK][BM];  // A values duplicated (lo==hi), 16 KB
    __shared__ float Bs[BK][BN];                // 8 KB

    const int bm  = blockIdx.y * BM;
    const int bn  = blockIdx.x * BN;
    const int tid = threadIdx.x;

    const int tr = (tid >> 4) * 8;    // row offset in tile
    const int tc = (tid & 15) * 8;    // col offset in tile

    unsigned long long acc[8][4];
#pragma unroll
    for (int i = 0; i < 8; i++)
#pragma unroll
        for (int j = 0; j < 4; j++)
            acc[i][j] = 0ULL;          // bits of (0.0f, 0.0f)

    const float* Ab = A + (size_t)bm * K_DIM;
    const float* Bb = B + (size_t)bn * K_DIM;

    for (int k0 = 0; k0 < K_DIM; k0 += BK) {
#pragma unroll
        for (int i = 0; i < 2; i++) {
            int idx = tid + i * 256;          // 0..511
            int row = idx >> 2;               // 0..127
            int kq  = (idx & 3) << 2;         // 0,4,8,12
            float4 av = *(const float4*)(Ab + (size_t)row * K_DIM + k0 + kq);
            As2[kq + 0][row] = dup2(av.x);
            As2[kq + 1][row] = dup2(av.y);
            As2[kq + 2][row] = dup2(av.z);
            As2[kq + 3][row] = dup2(av.w);
            float4 bv = *(const float4*)(Bb + (size_t)row * K_DIM + k0 + kq);
            Bs[kq + 0][row] = bv.x;
            Bs[kq + 1][row] = bv.y;
            Bs[kq + 2][row] = bv.z;
            Bs[kq + 3][row] = bv.w;
        }
        __syncthreads();

#pragma unroll
        for (int kk = 0; kk < BK; kk++) {
            unsigned long long a2[8];
#pragma unroll
            for (int i = 0; i < 8; i++)
                a2[i] = As2[kk][tr + i];           // broadcast LDS.64

            // 8 B values = 2x LDS.128 = 4 packed pairs
            ulonglong2 bql = *(const ulonglong2*)(&Bs[kk][tc]);
            ulonglong2 bqh = *(const ulonglong2*)(&Bs[kk][tc + 4]);
            unsigned long long b2[4] = { bql.x, bql.y, bqh.x, bqh.y };

#pragma unroll
            for (int i = 0; i < 8; i++)
#pragma unroll
                for (int j = 0; j < 4; j++)
                    ffma2(acc[i][j], a2[i], b2[j]);
        }
        __syncthreads();
    }

    // Epilogue: unpack, add bias, store (same arithmetic as scalar version)
#pragma unroll
    for (int i = 0; i < 8; i++) {
        size_t crow = (size_t)(bm + tr + i) * N_DIM + bn + tc;
        float o[8];
#pragma unroll
        for (int j = 0; j < 4; j++)
            unpack2(acc[i][j], o[2 * j], o[2 * j + 1]);
#pragma unroll
        for (int j = 0; j < 8; j += 4) {
            float4 ov;
            ov.x = o[j + 0] + bias[bn + tc + j + 0];
            ov.y = o[j + 1] + bias[bn + tc + j + 1];
            ov.z = o[j + 2] + bias[bn + tc + j + 2];
            ov.w = o[j + 3] + bias[bn + tc + j + 3];
            *(float4*)(C + crow + j) = ov;
        }
    }
}

// ---------------------------------------------------------------------------
// Kernel 2: GIF-neuron scan. One thread per (b, h) chain: 8192 threads,
// 128 blocks x 64 threads (spread over SMs; latency-chain bound).
//
// Fast path: rcp.approx + magic-constant floor off the critical chain,
// with an exact residual check. Any step where the fast spike could differ
// from the reference floor(RN(v/theta)) (off-by-one OR half-ulp RN boundary)
// sets a flag; the 16-step block is then redone with exact reference
// semantics. Non-flagged steps are bitwise identical to the slow path.
// ---------------------------------------------------------------------------
__global__ __launch_bounds__(64)
void gif_scan_kernel(const float* __restrict__ h,
                     float* __restrict__ spikes,
                     float* __restrict__ v_out,
                     float* __restrict__ theta_out)
{
    const int idx = blockIdx.x * blockDim.x + threadIdx.x;
    if (idx >= B_DIM * N_DIM) return;
    const int b  = idx >> 9;        // / 512
    const int hh = idx & 511;

    const float* hp = h      + (size_t)b * T_DIM * N_DIM + hh;
    float*       sp = spikes + (size_t)b * T_DIM * N_DIM + hh;

    const float DECAY = 0.90483741803595952f;  // exp(-1/10)
    const float MAGIC = 12582912.0f;           // 2^23 + 2^22

    float v = 0.0f;
    float theta = 1.0f;

    float cur[16];
#pragma unroll
    for (int u = 0; u < 16; u++)
        cur[u] = hp[(size_t)u * N_DIM];

    for (int t0 = 0; t0 < T_DIM; t0 += 16) {
        // Prefetch next block (hides L2/DRAM latency under ~800 cyc of compute)
        float nxt[16];
        if (t0 + 16 < T_DIM) {
#pragma unroll
            for (int u = 0; u < 16; u++)
                nxt[u] = hp[(size_t)(t0 + 16 + u) * N_DIM];
        } else {
#pragma unroll
            for (int u = 0; u < 16; u++)
                nxt[u] = 0.0f;
        }

        const float v_save  = v;
        const float th_save = theta;
        float out[16];
        int flag = 0;

#pragma unroll
        for (int u = 0; u < 16; u++) {
            v = fmaf(v, DECAY, cur[u]);
            float cl = 32.0f * theta;
            v = fminf(fmaxf(v, -cl), cl);

            // quotient estimate off the v-critical path
            float r;
            asm("rcp.approx.f32 %0, %1;" : "=f"(r) : "f"(theta));
            float qm = fmaf(v, r, -0.499999f);
            float t1 = __fadd_rn(qm, MAGIC);
            float s0 = __fsub_rn(t1, MAGIC);        // ~round(v/theta - 0.5) = floor estimate
            float s  = fminf(fmaxf(s0, 0.0f), 16.0f);

            float d = fmaf(-s, theta, v);           // residual; sign is exact
            float thHi = theta * 0.99999905f;       // theta*(1 - 2^-20)
            // flag: any possible deviation from floor(RN-div) semantics
            flag |= ((d < 0.0f) & (s > 0.0f)) | ((d >= thHi) & (s < 16.0f));

            v = d;                                  // v - s*theta (same fma as slow path)
            theta = theta + 0.01f * s - 0.01f * (theta - 1.0f);
            out[u] = s;
        }

        if (__builtin_expect(flag, 0)) {
            // exact reference-semantics redo of this 16-step block
            v = v_save;
            theta = th_save;
#pragma unroll
            for (int u = 0; u < 16; u++) {
                v = fmaf(v, DECAY, cur[u]);
                float cl = 32.0f * theta;
                v = fminf(fmaxf(v, -cl), cl);
                float s = floorf(v / theta);
                s = fminf(fmaxf(s, 0.0f), 16.0f);
                v = fmaf(-s, theta, v);
                theta = theta + 0.01f * s - 0.01f * (theta - 1.0f);
                out[u] = s;
            }
        }

#pragma unroll
        for (int u = 0; u < 16; u++)
            sp[(size_t)(t0 + u) * N_DIM] = out[u];

#pragma unroll
        for (int u = 0; u < 16; u++)
            cur[u] = nxt[u];
    }

    v_out[idx]     = v;
    theta_out[idx] = theta;
}

// ---------------------------------------------------------------------------
// kernel_launch
// Inputs (metadata order): x [16,2048,512] f32, W [512,512] f32, b [512] f32
// Output: float32, spikes | v_f | theta_f
// ---------------------------------------------------------------------------
extern "C" void kernel_launch(void* const* d_in, const int* in_sizes, int n_in,
                              void* d_out, int out_size)
{
    const float* x = (const float*)d_in[0];
    const float* W = (const float*)d_in[1];
    const float* b = (const float*)d_in[2];

    float* out    = (float*)d_out;
    float* spikes = out;
    float* v_f    = out + (size_t)B_DIM * T_DIM * N_DIM;
    float* th_f   = v_f + (size_t)B_DIM * N_DIM;

    float* h;
    cudaGetSymbolAddress((void**)&h, g_h);

    dim3 gemm_grid(N_DIM / BN, M_DIM / BM);   // (4, 256)
    gemm_nt_f32x2_kernel<<<gemm_grid, 256>>>(x, W, b, h);

    gif_scan_kernel<<<(B_DIM * N_DIM + 63) / 64, 64>>>(h, spikes, v_f, th_f);
}

// round 6
// speedup vs baseline: 1.2567x; 1.1476x over previous
#include <cuda_runtime.h>
#include <cuda_bf16.h>
#include <cstdint>

// ---------------------------------------------------------------------------
// GIFNeuron: h = x @ W^T + b  (M=32768, N=512, K=512, fp32)
// GEMM: scalar fp32 FFMA, sequential-k fma order (bit-exact vs reference —
// proven rel_err 0.0; fp32 datapath-peak bound, ~415us).
// Scan: shortened-chain fast path + exact-redo guard (bit-exact).
// Outputs flattened: spikes [B,T,H] | v_f [B,H] | theta_f [B,H]
// ---------------------------------------------------------------------------

#define M_DIM 32768   // B*T
#define N_DIM 512     // H
#define K_DIM 512     // IN
#define B_DIM 16
#define T_DIM 2048

// 64 MB scratch for h (static __device__ array: allocation-free)
__device__ float g_h[(size_t)M_DIM * N_DIM];

// ---------------------------------------------------------------------------
// Kernel 1: fp32 GEMM, C[m][n] = sum_k A[m][k] * B[n][k] + bias[n]
// (verbatim round-1 kernel: bit-exact vs reference, at fp32 datapath peak)
// ---------------------------------------------------------------------------
#define BM 128
#define BN 128
#define BK 16
#define TM 8
#define TN 8

__global__ __launch_bounds__(256, 2)
void gemm_nt_kernel(const float* __restrict__ A,
                    const float* __restrict__ B,
                    const float* __restrict__ bias,
                    float* __restrict__ C)
{
    __shared__ float As[BK][BM];
    __shared__ float Bs[BK][BN];

    const int bm  = blockIdx.y * BM;
    const int bn  = blockIdx.x * BN;
    const int tid = threadIdx.x;

    const int tr = (tid >> 4) * TM;   // 0..120, row offset in tile
    const int tc = (tid & 15) * TN;   // 0..120, col offset in tile

    float acc[TM][TN];
#pragma unroll
    for (int i = 0; i < TM; i++)
#pragma unroll
        for (int j = 0; j < TN; j++)
            acc[i][j] = 0.0f;

    const float* Ab = A + (size_t)bm * K_DIM;
    const float* Bb = B + (size_t)bn * K_DIM;

    for (int k0 = 0; k0 < K_DIM; k0 += BK) {
#pragma unroll
        for (int i = 0; i < 2; i++) {
            int idx = tid + i * 256;          // 0..511
            int row = idx >> 2;               // 0..127
            int kq  = (idx & 3) << 2;         // 0,4,8,12
            float4 av = *(const float4*)(Ab + (size_t)row * K_DIM + k0 + kq);
            As[kq + 0][row] = av.x;
            As[kq + 1][row] = av.y;
            As[kq + 2][row] = av.z;
            As[kq + 3][row] = av.w;
            float4 bv = *(const float4*)(Bb + (size_t)row * K_DIM + k0 + kq);
            Bs[kq + 0][row] = bv.x;
            Bs[kq + 1][row] = bv.y;
            Bs[kq + 2][row] = bv.z;
            Bs[kq + 3][row] = bv.w;
        }
        __syncthreads();

#pragma unroll
        for (int kk = 0; kk < BK; kk++) {
            float ar[TM], br[TN];
#pragma unroll
            for (int i = 0; i < TM; i++) ar[i] = As[kk][tr + i];
#pragma unroll
            for (int j = 0; j < TN; j++) br[j] = Bs[kk][tc + j];
#pragma unroll
            for (int i = 0; i < TM; i++)
#pragma unroll
                for (int j = 0; j < TN; j++)
                    acc[i][j] = fmaf(ar[i], br[j], acc[i][j]);
        }
        __syncthreads();
    }

#pragma unroll
    for (int i = 0; i < TM; i++) {
        size_t crow = (size_t)(bm + tr + i) * N_DIM + bn + tc;
#pragma unroll
        for (int j = 0; j < TN; j += 4) {
            float4 o;
            o.x = acc[i][j + 0] + bias[bn + tc + j + 0];
            o.y = acc[i][j + 1] + bias[bn + tc + j + 1];
            o.z = acc[i][j + 2] + bias[bn + tc + j + 2];
            o.w = acc[i][j + 3] + bias[bn + tc + j + 3];
            *(float4*)(C + crow + j) = o;
        }
    }
}

// ---------------------------------------------------------------------------
// Kernel 2: GIF-neuron scan. One thread per (b, h): 8192 threads = 256 x 32
// (one warp per SMSP across 256 SMSPs -> max per-warp issue bandwidth).
//
// Fast path per step (v-chain = 6 fma-class ops ~ 24 cyc):
//   vin = fma(v, DECAY, in)
//   s   = magic-round( max(fma(vin, rcp(theta), -0.499999), -0.25) )
//   v   = fma(-s, theta, vin)
// Off-chain float max-trackers flag (conservatively, with exact/Sterbenz
// subtractions) every case where this could deviate from reference
// semantics: clamp engage, s>=17 clip, s one-too-big (residual<0),
// s possibly-too-small / RN-division boundary. A flagged 32-step block is
// re-run with the exact round-1 code (bit-identical). Accepted steps are
// bitwise equal to the round-1 passing kernel by construction.
// ---------------------------------------------------------------------------
__global__ __launch_bounds__(32)
void gif_scan_kernel(float* __restrict__ spikes,
                     float* __restrict__ v_out,
                     float* __restrict__ theta_out)
{
    const int idx = blockIdx.x * 32 + threadIdx.x;
    if (idx >= B_DIM * N_DIM) return;
    const int b  = idx >> 9;
    const int hh = idx & 511;

    const float* hp = g_h    + (size_t)b * T_DIM * N_DIM + hh;
    float*       sp = spikes + (size_t)b * T_DIM * N_DIM + hh;

    const float DECAY = 0.90483741803595952f;   // exp(-1/10)
    const float MAGIC = 12582912.0f;            // 2^23 + 2^22

    float v = 0.0f;
    float theta = 1.0f;
    float r = 1.0f;                              // ~1/theta (rcp.approx)

    float cur[32];
#pragma unroll
    for (int u = 0; u < 32; u++)
        cur[u] = hp[(size_t)u * N_DIM];

    for (int t0 = 0; t0 < T_DIM; t0 += 32) {
        // Prefetch next 32 inputs: issued ~770+ chain-cycles before use.
        float nxt[32];
        if (t0 + 32 < T_DIM) {
#pragma unroll
            for (int u = 0; u < 32; u++)
                nxt[u] = hp[(size_t)(t0 + 32 + u) * N_DIM];
        } else {
#pragma unroll
            for (int u = 0; u < 32; u++)
                nxt[u] = 0.0f;
        }

        const float v_save  = v;
        const float th_save = theta;
        float out[32];
        float bad = -1.0f;

#pragma unroll
        for (int u = 0; u < 32; u++) {
            float vin = fmaf(v, DECAY, cur[u]);                 // chain
            float qm  = fmaf(vin, r, -0.499999f);               // chain
            float qc  = fmaxf(qm, -0.25f);                      // chain (forces s>=0)
            float t1  = __fadd_rn(qc, MAGIC);                   // chain
            float s   = __fsub_rn(t1, MAGIC);                   // chain: integer >= 0
            float d   = fmaf(-s, theta, vin);                   // chain -> next v

            // --- off-chain flag trackers (fire => exact redo; always safe) ---
            float cl = 32.0f * theta;                           // exact (x32)
            bad = fmaxf(bad, fabsf(vin) - cl);                  // clamp would engage
            bad = fmaxf(bad, s - 16.5f);                        // s >= 17: clip engages
            bad = fmaxf(bad, fminf(-d, s - 0.5f));              // d<0 && s>0: s too big
            bad = fmaxf(bad, d - theta * 0.999996f);            // s too small / RN boundary

            v = d;
            theta = theta + 0.01f * s - 0.01f * (theta - 1.0f);
            asm("rcp.approx.f32 %0, %1;" : "=f"(r) : "f"(theta));
            out[u] = s;
        }

        if (__builtin_expect(bad >= 0.0f, 0)) {
            // Exact reference-semantics redo (verbatim round-1 step code)
            v = v_save;
            theta = th_save;
#pragma unroll
            for (int u = 0; u < 32; u++) {
                v = fmaf(v, DECAY, cur[u]);
                float cl = 32.0f * theta;
                v = fminf(fmaxf(v, -cl), cl);
                float s = floorf(v / theta);
                s = fminf(fmaxf(s, 0.0f), 16.0f);
                v = fmaf(-s, theta, v);
                theta = theta + 0.01f * s - 0.01f * (theta - 1.0f);
                out[u] = s;
            }
            asm("rcp.approx.f32 %0, %1;" : "=f"(r) : "f"(theta));
        }

#pragma unroll
        for (int u = 0; u < 32; u++)
            sp[(size_t)(t0 + u) * N_DIM] = out[u];

#pragma unroll
        for (int u = 0; u < 32; u++)
            cur[u] = nxt[u];
    }

    v_out[idx]     = v;
    theta_out[idx] = theta;
}

// ---------------------------------------------------------------------------
// kernel_launch
// Inputs (metadata order): x [16,2048,512] f32, W [512,512] f32, b [512] f32
// Output: float32, spikes | v_f | theta_f
// ---------------------------------------------------------------------------
extern "C" void kernel_launch(void* const* d_in, const int* in_sizes, int n_in,
                              void* d_out, int out_size)
{
    const float* x = (const float*)d_in[0];
    const float* W = (const float*)d_in[1];
    const float* b = (const float*)d_in[2];

    float* out    = (float*)d_out;
    float* spikes = out;
    float* v_f    = out + (size_t)B_DIM * T_DIM * N_DIM;
    float* th_f   = v_f + (size_t)B_DIM * N_DIM;

    float* h;
    cudaGetSymbolAddress((void**)&h, g_h);

    dim3 gemm_grid(N_DIM / BN, M_DIM / BM);   // (4, 256)
    gemm_nt_kernel<<<gemm_grid, 256>>>(x, W, b, h);

    gif_scan_kernel<<<B_DIM * N_DIM / 32, 32>>>(spikes, v_f, th_f);
}